// round 16
// baseline (speedup 1.0000x reference)
#include <cuda_runtime.h>
#include <cstdint>
#include <cfloat>

#define NEG_SLOPE 0.01f

constexpr int Vv = 32, Fv = 16, Hv = 64;
constexpr int NG = 16384;            // (b,p) groups
constexpr int GPP = 4;               // groups per pass
constexpr int NPASS = NG / GPP;      // 4096
constexpr int THREADS = 256;
constexpr int STRIDE = 68;           // padded activation row stride (proven conflict-free)
constexpr int GRID = 444;            // 3 blocks/SM * 148 SMs

// Shared float layout (74496 B -> 3 blocks/SM):
constexpr int OFF_W1  = 0;         // 1024
constexpr int OFF_W2O = 1024;      // 4096 out-half [h][64]
constexpr int OFF_W3O = 5120;      // 4096
constexpr int OFF_B1  = 9216;
constexpr int OFF_B2  = 9280;
constexpr int OFF_B3  = 9344;
constexpr int OFF_PL1 = 9408;      // 256 [GPP][64]
constexpr int OFF_PL2 = 9664;      // 256
constexpr int OFF_BUF = 9920;      // 8704 [GPP][32][STRIDE]
constexpr int SMEM_FLOATS = 18624;
constexpr int SMEM_BYTES  = SMEM_FLOATS * 4;   // 74496

// Warp max via integer redux (sm_80+ s32 redux; .f32 variant is what sm_103 lacks).
// Order-preserving self-inverse key: k = i ^ ((i>>31) & 0x7fffffff).
__device__ __forceinline__ float warp_max_f32(float f) {
    int i = __float_as_int(f);
    int key = i ^ ((i >> 31) & 0x7fffffff);
    int r;
    asm volatile("redux.sync.max.s32 %0, %1, 0xffffffff;" : "=r"(r) : "r"(key));
    return __int_as_float(r ^ ((r >> 31) & 0x7fffffff));
}

__global__ __launch_bounds__(THREADS, 3)
void fused_mlp_pool_kernel(const float* __restrict__ x,
                           const void*  __restrict__ maskp,
                           const float* __restrict__ W1,
                           const float* __restrict__ b1,
                           const float* __restrict__ W2,
                           const float* __restrict__ b2,
                           const float* __restrict__ W3,
                           const float* __restrict__ b3,
                           float* __restrict__ out)
{
    extern __shared__ float sm[];
    float* W1s = sm + OFF_W1;
    float* W2o = sm + OFF_W2O;
    float* W3o = sm + OFF_W3O;
    float* b1s = sm + OFF_B1;
    float* b2s = sm + OFF_B2;
    float* b3s = sm + OFF_B3;
    float* pl1 = sm + OFF_PL1;
    float* pl2 = sm + OFF_PL2;
    float* buf = sm + OFF_BUF;

    const int tid  = threadIdx.x;
    const int lane = tid & 31;      // = v
    const int warp = tid >> 5;      // 0..7
    const int hbase = warp * 8;

    // pool-const lane ownership: lane handles h_own = hbase + (lane>>2), j-slice (lane&3)*16..+16
    const int h_own = hbase + (lane >> 2);
    const int jq    = (lane & 3) * 16;

    // ---- stage W1 + OUT-halves of W2/W3 + biases into shared ----
    for (int i = tid; i < 1024; i += THREADS) W1s[i] = W1[i];
    for (int i = tid; i < 4096; i += THREADS) {
        int h = i >> 6, j = i & 63;
        W2o[i] = W2[h * 128 + j];
        W3o[i] = W3[h * 128 + j];
    }
    if (tid < 64) { b1s[tid] = b1[tid]; b2s[tid] = b2[tid]; b3s[tid] = b3[tid]; }

    // ---- detect mask encoding (bool-u8 / int32 / float32) ----
    __shared__ int s_flags[4];
    if (tid < 4) s_flags[tid] = 0;
    __syncthreads();
    {
        int f0 = 0, f1 = 0, f23 = 0;
        const unsigned char* mb = (const unsigned char*)maskp;
        #pragma unroll
        for (int i = 0; i < 16; i++) {
            int idx = tid * 16 + i;
            unsigned char c = mb[idx];
            if (c) { int m = idx & 3; if (m == 0) f0 = 1; else if (m == 1) f1 = 1; else f23 = 1; }
        }
        if (f0)  atomicOr(&s_flags[0], 1);
        if (f1)  atomicOr(&s_flags[1], 1);
        if (f23) atomicOr(&s_flags[2], 1);
    }
    __syncthreads();
    const int fmt = s_flags[1] ? 1 : (s_flags[0] ? 0 : (s_flags[2] ? 2 : 0));

    // Global pool-half weight slices for this lane's owned h (L1-resident after pass 1).
    const float4* W2p_own = (const float4*)(W2 + h_own * 128 + 64 + jq);
    const float4* W3p_own = (const float4*)(W3 + h_own * 128 + 64 + jq);

    for (int pass = blockIdx.x; pass < NPASS; pass += gridDim.x) {
        const int g0 = pass * GPP;

        bool valid[GPP], anyv[GPP];
        #pragma unroll
        for (int gi = 0; gi < GPP; gi++) {
            const int midx = (g0 + gi) * Vv + lane;
            bool v;
            if (fmt == 1)      v = ((const unsigned char*)maskp)[midx] != 0;
            else if (fmt == 0) v = ((const int*)maskp)[midx] != 0;
            else               v = ((const float*)maskp)[midx] != 0.0f;
            valid[gi] = v;
            anyv[gi]  = __ballot_sync(0xffffffffu, v) != 0;
        }

        // ================= Layer 1: 16 -> 64, per group =================
        #pragma unroll 1
        for (int gi = 0; gi < GPP; gi++) {
            const float4* xp = (const float4*)(x + ((size_t)(g0 + gi) * Vv + lane) * Fv);
            float4 x0 = xp[0], x1 = xp[1], x2 = xp[2], x3 = xp[3];
            float o[8], m[8];
            #pragma unroll
            for (int hh = 0; hh < 8; hh++) {
                const float4* w = (const float4*)(W1s + (hbase + hh) * 16);
                float4 w0 = w[0], w1 = w[1], w2 = w[2], w3 = w[3];
                float s = b1s[hbase + hh];
                s = fmaf(x0.x, w0.x, s); s = fmaf(x0.y, w0.y, s); s = fmaf(x0.z, w0.z, s); s = fmaf(x0.w, w0.w, s);
                s = fmaf(x1.x, w1.x, s); s = fmaf(x1.y, w1.y, s); s = fmaf(x1.z, w1.z, s); s = fmaf(x1.w, w1.w, s);
                s = fmaf(x2.x, w2.x, s); s = fmaf(x2.y, w2.y, s); s = fmaf(x2.z, w2.z, s); s = fmaf(x2.w, w2.w, s);
                s = fmaf(x3.x, w3.x, s); s = fmaf(x3.y, w3.y, s); s = fmaf(x3.z, w3.z, s); s = fmaf(x3.w, w3.w, s);
                float r = s > 0.0f ? s : NEG_SLOPE * s;
                o[hh] = valid[gi] ? r : 0.0f;
                m[hh] = warp_max_f32(valid[gi] ? r : -FLT_MAX);
            }
            float* row = buf + gi * (Vv * STRIDE) + lane * STRIDE + hbase;
            *(float4*)(row)     = make_float4(o[0], o[1], o[2], o[3]);
            *(float4*)(row + 4) = make_float4(o[4], o[5], o[6], o[7]);
            if (lane == 0) {
                float* pp = pl1 + gi * 64 + hbase;
                *(float4*)(pp)     = make_float4(anyv[gi] ? m[0] : 0.0f, anyv[gi] ? m[1] : 0.0f,
                                                 anyv[gi] ? m[2] : 0.0f, anyv[gi] ? m[3] : 0.0f);
                *(float4*)(pp + 4) = make_float4(anyv[gi] ? m[4] : 0.0f, anyv[gi] ? m[5] : 0.0f,
                                                 anyv[gi] ? m[6] : 0.0f, anyv[gi] ? m[7] : 0.0f);
            }
        }
        __syncthreads();   // sync1: L1 writes -> L2 reads

        float acc[GPP][8];

        // ======= L2 pool-const, lane-parallel: c[h] = b2[h] + sum_j pl1[j]*W2[h][64+j] =======
        {
            float4 wq0 = __ldg(W2p_own), wq1 = __ldg(W2p_own + 1),
                   wq2 = __ldg(W2p_own + 2), wq3 = __ldg(W2p_own + 3);
            #pragma unroll
            for (int gi = 0; gi < GPP; gi++) {
                const float4* pq = (const float4*)(pl1 + gi * 64 + jq);
                float4 p0 = pq[0], p1 = pq[1], p2 = pq[2], p3 = pq[3];
                float s = p0.x * wq0.x;
                s = fmaf(p0.y, wq0.y, s); s = fmaf(p0.z, wq0.z, s); s = fmaf(p0.w, wq0.w, s);
                s = fmaf(p1.x, wq1.x, s); s = fmaf(p1.y, wq1.y, s); s = fmaf(p1.z, wq1.z, s); s = fmaf(p1.w, wq1.w, s);
                s = fmaf(p2.x, wq2.x, s); s = fmaf(p2.y, wq2.y, s); s = fmaf(p2.z, wq2.z, s); s = fmaf(p2.w, wq2.w, s);
                s = fmaf(p3.x, wq3.x, s); s = fmaf(p3.y, wq3.y, s); s = fmaf(p3.z, wq3.z, s); s = fmaf(p3.w, wq3.w, s);
                s += __shfl_xor_sync(0xffffffffu, s, 1);
                s += __shfl_xor_sync(0xffffffffu, s, 2);   // all 4 lanes of group hold c[h_own]
                #pragma unroll
                for (int hh = 0; hh < 8; hh++)
                    acc[gi][hh] = __shfl_sync(0xffffffffu, s, hh * 4) + b2s[hbase + hh];
            }
        }
        #pragma unroll 2
        for (int j = 0; j < 64; j += 4) {
            float4 a[GPP];
            #pragma unroll
            for (int gi = 0; gi < GPP; gi++)
                a[gi] = *(const float4*)(buf + gi * (Vv * STRIDE) + lane * STRIDE + j);
            #pragma unroll
            for (int hc = 0; hc < 2; hc++) {
                float4 w[4];
                #pragma unroll
                for (int hh = 0; hh < 4; hh++)
                    w[hh] = *(const float4*)(W2o + (hbase + hc * 4 + hh) * 64 + j);
                #pragma unroll
                for (int gi = 0; gi < GPP; gi++)
                    #pragma unroll
                    for (int hh = 0; hh < 4; hh++)
                        acc[gi][hc * 4 + hh] = fmaf(a[gi].x, w[hh].x, fmaf(a[gi].y, w[hh].y,
                                               fmaf(a[gi].z, w[hh].z, fmaf(a[gi].w, w[hh].w,
                                                    acc[gi][hc * 4 + hh]))));
            }
        }
        __syncthreads();   // sync2: L2 reads done before in-place writes

        // epilogue L2 -> buf (in place), pl2
        #pragma unroll
        for (int gi = 0; gi < GPP; gi++) {
            float o[8], m[8];
            #pragma unroll
            for (int hh = 0; hh < 8; hh++) {
                float r = acc[gi][hh] > 0.0f ? acc[gi][hh] : NEG_SLOPE * acc[gi][hh];
                o[hh] = valid[gi] ? r : 0.0f;
                m[hh] = warp_max_f32(valid[gi] ? r : -FLT_MAX);
            }
            float* row = buf + gi * (Vv * STRIDE) + lane * STRIDE + hbase;
            *(float4*)(row)     = make_float4(o[0], o[1], o[2], o[3]);
            *(float4*)(row + 4) = make_float4(o[4], o[5], o[6], o[7]);
            if (lane == 0) {
                float* pp = pl2 + gi * 64 + hbase;
                *(float4*)(pp)     = make_float4(anyv[gi] ? m[0] : 0.0f, anyv[gi] ? m[1] : 0.0f,
                                                 anyv[gi] ? m[2] : 0.0f, anyv[gi] ? m[3] : 0.0f);
                *(float4*)(pp + 4) = make_float4(anyv[gi] ? m[4] : 0.0f, anyv[gi] ? m[5] : 0.0f,
                                                 anyv[gi] ? m[6] : 0.0f, anyv[gi] ? m[7] : 0.0f);
            }
        }
        __syncthreads();   // sync3: L2 writes -> L3 reads

        // ======= L3 pool-const, lane-parallel =======
        {
            float4 wq0 = __ldg(W3p_own), wq1 = __ldg(W3p_own + 1),
                   wq2 = __ldg(W3p_own + 2), wq3 = __ldg(W3p_own + 3);
            #pragma unroll
            for (int gi = 0; gi < GPP; gi++) {
                const float4* pq = (const float4*)(pl2 + gi * 64 + jq);
                float4 p0 = pq[0], p1 = pq[1], p2 = pq[2], p3 = pq[3];
                float s = p0.x * wq0.x;
                s = fmaf(p0.y, wq0.y, s); s = fmaf(p0.z, wq0.z, s); s = fmaf(p0.w, wq0.w, s);
                s = fmaf(p1.x, wq1.x, s); s = fmaf(p1.y, wq1.y, s); s = fmaf(p1.z, wq1.z, s); s = fmaf(p1.w, wq1.w, s);
                s = fmaf(p2.x, wq2.x, s); s = fmaf(p2.y, wq2.y, s); s = fmaf(p2.z, wq2.z, s); s = fmaf(p2.w, wq2.w, s);
                s = fmaf(p3.x, wq3.x, s); s = fmaf(p3.y, wq3.y, s); s = fmaf(p3.z, wq3.z, s); s = fmaf(p3.w, wq3.w, s);
                s += __shfl_xor_sync(0xffffffffu, s, 1);
                s += __shfl_xor_sync(0xffffffffu, s, 2);
                #pragma unroll
                for (int hh = 0; hh < 8; hh++)
                    acc[gi][hh] = __shfl_sync(0xffffffffu, s, hh * 4) + b3s[hbase + hh];
            }
        }
        #pragma unroll 2
        for (int j = 0; j < 64; j += 4) {
            float4 a[GPP];
            #pragma unroll
            for (int gi = 0; gi < GPP; gi++)
                a[gi] = *(const float4*)(buf + gi * (Vv * STRIDE) + lane * STRIDE + j);
            #pragma unroll
            for (int hc = 0; hc < 2; hc++) {
                float4 w[4];
                #pragma unroll
                for (int hh = 0; hh < 4; hh++)
                    w[hh] = *(const float4*)(W3o + (hbase + hc * 4 + hh) * 64 + j);
                #pragma unroll
                for (int gi = 0; gi < GPP; gi++)
                    #pragma unroll
                    for (int hh = 0; hh < 4; hh++)
                        acc[gi][hc * 4 + hh] = fmaf(a[gi].x, w[hh].x, fmaf(a[gi].y, w[hh].y,
                                               fmaf(a[gi].z, w[hh].z, fmaf(a[gi].w, w[hh].w,
                                                    acc[gi][hc * 4 + hh]))));
            }
        }
        // final epilogue: pool3 -> out
        #pragma unroll
        for (int gi = 0; gi < GPP; gi++) {
            float m[8];
            #pragma unroll
            for (int hh = 0; hh < 8; hh++) {
                float r = acc[gi][hh] > 0.0f ? acc[gi][hh] : NEG_SLOPE * acc[gi][hh];
                m[hh] = warp_max_f32(valid[gi] ? r : -FLT_MAX);
            }
            if (lane == 0) {
                float* op = out + (size_t)(g0 + gi) * Hv + hbase;
                *(float4*)(op)     = make_float4(anyv[gi] ? m[0] : 0.0f, anyv[gi] ? m[1] : 0.0f,
                                                 anyv[gi] ? m[2] : 0.0f, anyv[gi] ? m[3] : 0.0f);
                *(float4*)(op + 4) = make_float4(anyv[gi] ? m[4] : 0.0f, anyv[gi] ? m[5] : 0.0f,
                                                 anyv[gi] ? m[6] : 0.0f, anyv[gi] ? m[7] : 0.0f);
            }
        }
        __syncthreads();   // sync4: L3 reads done before next pass's L1 writes
    }
}

extern "C" void kernel_launch(void* const* d_in, const int* in_sizes, int n_in,
                              void* d_out, int out_size)
{
    const float* x  = (const float*)d_in[0];
    const void*  mk = d_in[1];
    const float* W1 = (const float*)d_in[2];
    const float* b1 = (const float*)d_in[3];
    const float* W2 = (const float*)d_in[4];
    const float* b2 = (const float*)d_in[5];
    const float* W3 = (const float*)d_in[6];
    const float* b3 = (const float*)d_in[7];
    float* out = (float*)d_out;

    cudaFuncSetAttribute(fused_mlp_pool_kernel,
                         cudaFuncAttributeMaxDynamicSharedMemorySize, SMEM_BYTES);
    fused_mlp_pool_kernel<<<GRID, THREADS, SMEM_BYTES>>>(x, mk, W1, b1, W2, b2, W3, b3, out);
}